// round 1
// baseline (speedup 1.0000x reference)
#include <cuda_runtime.h>
#include <cuda_bf16.h>
#include <math.h>

// Problem constants
#define FEAT_DIM 512
#define H_DIM    512
#define DEPTH    17
#define N_NODES  ((1 << DEPTH) - 1)   // 131071
#define GATE5    (5 * H_DIM)          // 2560
#define MAX_PREV (1 << (DEPTH - 2))   // 32768 rows max for recurrent GEMM

// ---------------------------------------------------------------------------
// Scratch (static __device__ allocations; no cudaMalloc allowed)
// ---------------------------------------------------------------------------
__device__ float g_iofux[(size_t)N_NODES * GATE5];  // feats @ iofux_w.T  (1.34 GB)
__device__ float g_px   [(size_t)N_NODES * H_DIM];  // feats @ px_w.T     (268 MB)
__device__ float g_c    [(size_t)N_NODES * H_DIM];  // cell state per node (268 MB)
__device__ float g_hh   [(size_t)MAX_PREV * GATE5]; // prev_h @ iofuh_w.T (335 MB)

// ---------------------------------------------------------------------------
// fp32 tiled GEMM:  C[M,N] = A[M,K] @ B[N,K]^T
// A row-major [M,K], B row-major [N,K] (PyTorch/JAX weight layout), K%8==0,
// N%128==0. M edge predicated. 128x128 tile, BK=8, 256 thr, 8x8 per thread.
// ---------------------------------------------------------------------------
#define TS 128
__global__ void __launch_bounds__(256) sgemm_tn(
    const float* __restrict__ A, const float* __restrict__ B,
    float* __restrict__ C, int M, int N, int K)
{
    __shared__ float As[8][TS];
    __shared__ float Bs[8][TS];

    const int tid     = threadIdx.x;
    const int loadRow = tid >> 1;          // 0..127
    const int loadK   = (tid & 1) << 2;    // 0 or 4
    const int aRow    = blockIdx.y * TS + loadRow;
    const int bCol    = blockIdx.x * TS + loadRow;
    const bool aValid = (aRow < M);

    const float* Ap = A + (size_t)(aValid ? aRow : 0) * K + loadK;
    const float* Bp = B + (size_t)bCol * K + loadK;

    const int tx = tid & 15;   // col group
    const int ty = tid >> 4;   // row group

    float acc[8][8];
#pragma unroll
    for (int i = 0; i < 8; i++)
#pragma unroll
        for (int j = 0; j < 8; j++) acc[i][j] = 0.f;

    for (int k0 = 0; k0 < K; k0 += 8) {
        float4 av = *(const float4*)(Ap + k0);
        if (!aValid) av = make_float4(0.f, 0.f, 0.f, 0.f);
        float4 bv = *(const float4*)(Bp + k0);

        __syncthreads();
        As[loadK + 0][loadRow] = av.x; As[loadK + 1][loadRow] = av.y;
        As[loadK + 2][loadRow] = av.z; As[loadK + 3][loadRow] = av.w;
        Bs[loadK + 0][loadRow] = bv.x; Bs[loadK + 1][loadRow] = bv.y;
        Bs[loadK + 2][loadRow] = bv.z; Bs[loadK + 3][loadRow] = bv.w;
        __syncthreads();

#pragma unroll
        for (int kk = 0; kk < 8; kk++) {
            float4 a0 = *(const float4*)&As[kk][ty * 8];
            float4 a1 = *(const float4*)&As[kk][ty * 8 + 4];
            float4 b0 = *(const float4*)&Bs[kk][tx * 8];
            float4 b1 = *(const float4*)&Bs[kk][tx * 8 + 4];
            float a[8] = {a0.x, a0.y, a0.z, a0.w, a1.x, a1.y, a1.z, a1.w};
            float b[8] = {b0.x, b0.y, b0.z, b0.w, b1.x, b1.y, b1.z, b1.w};
#pragma unroll
            for (int i = 0; i < 8; i++)
#pragma unroll
                for (int j = 0; j < 8; j++)
                    acc[i][j] = fmaf(a[i], b[j], acc[i][j]);
        }
    }

#pragma unroll
    for (int i = 0; i < 8; i++) {
        int row = blockIdx.y * TS + ty * 8 + i;
        if (row < M) {
            float* Cp = C + (size_t)row * N + blockIdx.x * TS + tx * 8;
            *(float4*)(Cp)     = make_float4(acc[i][0], acc[i][1], acc[i][2], acc[i][3]);
            *(float4*)(Cp + 4) = make_float4(acc[i][4], acc[i][5], acc[i][6], acc[i][7]);
        }
    }
}

// ---------------------------------------------------------------------------
// Per-level fused gate/elementwise kernel.
// iofu = g_iofux[node] + iofux_b + g_hh[j>>1] + iofuh_b
// c = sig(i)*tanh(u) + sig(f)*pc ; h = sig(o)*tanh(c)
// h_final = sig(r)*h + (1-sig(r))*(g_px[node]+px_b)
// ---------------------------------------------------------------------------
__device__ __forceinline__ float sigf(float x) { return 1.f / (1.f + expf(-x)); }
__device__ __forceinline__ float4 f4add(float4 a, float4 b) {
    return make_float4(a.x + b.x, a.y + b.y, a.z + b.z, a.w + b.w);
}

__global__ void __launch_bounds__(256) lstm_level_kernel(
    const float* __restrict__ iofux_b, const float* __restrict__ iofuh_b,
    const float* __restrict__ px_b, float* __restrict__ out,
    int start, int n, int hasPrev)
{
    int idx = blockIdx.x * 256 + threadIdx.x;   // float4 granularity
    int total = n * (H_DIM / 4);
    if (idx >= total) return;

    int j  = idx >> 7;         // node index within level
    int t4 = idx & 127;        // float4 column
    size_t g = (size_t)start + j;

    const float4* gx = (const float4*)(g_iofux + g * GATE5);
    float4 vi = gx[t4];
    float4 vo = gx[128 + t4];
    float4 vf = gx[256 + t4];
    float4 vu = gx[384 + t4];
    float4 vr = gx[512 + t4];

    float4 pc = make_float4(0.f, 0.f, 0.f, 0.f);
    if (hasPrev) {
        const float4* gh = (const float4*)(g_hh + (size_t)(j >> 1) * GATE5);
        vi = f4add(vi, gh[t4]);
        vo = f4add(vo, gh[128 + t4]);
        vf = f4add(vf, gh[256 + t4]);
        vu = f4add(vu, gh[384 + t4]);
        vr = f4add(vr, gh[512 + t4]);
        size_t parent = (g - 1) >> 1;
        pc = ((const float4*)g_c)[parent * 128 + t4];
    }

    const float4* bx = (const float4*)iofux_b;
    const float4* bh = (const float4*)iofuh_b;
    vi = f4add(vi, f4add(bx[t4],       bh[t4]));
    vo = f4add(vo, f4add(bx[128 + t4], bh[128 + t4]));
    vf = f4add(vf, f4add(bx[256 + t4], bh[256 + t4]));
    vu = f4add(vu, f4add(bx[384 + t4], bh[384 + t4]));
    vr = f4add(vr, f4add(bx[512 + t4], bh[512 + t4]));

    float4 px4 = f4add(((const float4*)g_px)[g * 128 + t4],
                       ((const float4*)px_b)[t4]);

    float4 c4, h4;
#define GATE(C) {                                                     \
        float i_ = sigf(vi.C); float o_ = sigf(vo.C);                 \
        float f_ = sigf(vf.C); float u_ = tanhf(vu.C);                \
        float r_ = sigf(vr.C);                                        \
        float c_ = i_ * u_ + f_ * pc.C;                               \
        float h_ = o_ * tanhf(c_);                                    \
        c4.C = c_; h4.C = r_ * h_ + (1.f - r_) * px4.C; }
    GATE(x) GATE(y) GATE(z) GATE(w)
#undef GATE

    ((float4*)g_c)[g * 128 + t4] = c4;
    ((float4*)out)[g * 128 + t4] = h4;
}

// ---------------------------------------------------------------------------
// kernel_launch: 2 big GEMMs + 17 levels (recurrent GEMM + fused gates)
// ---------------------------------------------------------------------------
extern "C" void kernel_launch(void* const* d_in, const int* in_sizes, int n_in,
                              void* d_out, int out_size)
{
    const float* features = (const float*)d_in[0];
    const float* px_w     = (const float*)d_in[1];
    const float* px_b     = (const float*)d_in[2];
    const float* iofux_w  = (const float*)d_in[3];
    const float* iofux_b  = (const float*)d_in[4];
    const float* iofuh_w  = (const float*)d_in[5];
    const float* iofuh_b  = (const float*)d_in[6];
    float* out = (float*)d_out;

    float *iofux_p = nullptr, *px_p = nullptr, *hh_p = nullptr;
    cudaGetSymbolAddress((void**)&iofux_p, g_iofux);
    cudaGetSymbolAddress((void**)&px_p,    g_px);
    cudaGetSymbolAddress((void**)&hh_p,    g_hh);

    dim3 blk(256);

    // Precompute px = feats @ px_w.T   [N_NODES, 512]
    {
        dim3 grid(H_DIM / TS, (N_NODES + TS - 1) / TS);
        sgemm_tn<<<grid, blk>>>(features, px_w, px_p, N_NODES, H_DIM, FEAT_DIM);
    }
    // Precompute iofux = feats @ iofux_w.T  [N_NODES, 2560]
    {
        dim3 grid(GATE5 / TS, (N_NODES + TS - 1) / TS);
        sgemm_tn<<<grid, blk>>>(features, iofux_w, iofux_p, N_NODES, GATE5, FEAT_DIM);
    }

    // Level-by-level recurrence
    for (int d = 0; d < DEPTH; d++) {
        int n = 1 << d;
        int start = n - 1;
        if (d > 0) {
            int Md = n >> 1;
            int startPrev = Md - 1;
            // hh = prev_h_final @ iofuh_w.T  [Md, 2560]
            dim3 grid(GATE5 / TS, (Md + TS - 1) / TS);
            sgemm_tn<<<grid, blk>>>(out + (size_t)startPrev * H_DIM,
                                    iofuh_w, hh_p, Md, GATE5, FEAT_DIM);
        }
        int total = n * (H_DIM / 4);
        int nb = (total + 255) / 256;
        lstm_level_kernel<<<nb, blk>>>(iofux_b, iofuh_b, px_b, out,
                                       start, n, d > 0 ? 1 : 0);
    }
}

// round 2
// speedup vs baseline: 4.3356x; 4.3356x over previous
#include <cuda_runtime.h>
#include <cuda_bf16.h>
#include <math.h>
#include <stdint.h>

// Problem constants
#define FEAT_DIM 512
#define H_DIM    512
#define DEPTH    17
#define N_NODES  ((1 << DEPTH) - 1)   // 131071
#define GATE5    (5 * H_DIM)          // 2560
#define MAX_PREV (1 << (DEPTH - 2))   // 32768 rows max for recurrent GEMM

// ---------------------------------------------------------------------------
// Scratch (static __device__ allocations; no cudaMalloc allowed)
// ---------------------------------------------------------------------------
__device__ float g_iofux[(size_t)N_NODES * GATE5];  // feats @ iofux_w.T  (1.34 GB)
__device__ float g_px   [(size_t)N_NODES * H_DIM];  // feats @ px_w.T     (268 MB)
__device__ float g_c    [(size_t)N_NODES * H_DIM];  // cell state per node (268 MB)
__device__ float g_hh   [(size_t)MAX_PREV * GATE5]; // prev_h @ iofuh_w.T (335 MB)

// ---------------------------------------------------------------------------
// tf32 tensor-core GEMM: C[M,N] = A[M,K] @ B[N,K]^T
// A row-major [M,K] fp32, B row-major [N,K] fp32. K%16==0, N%128==0.
// Block tile 128x128, BK=16, 256 threads = 8 warps, each warp 32x64.
// mma.sync.aligned.m16n8k8 tf32. Inputs rounded RNA to tf32 at SMEM store.
// SMEM row stride = 20 floats => conflict-free fragment LDS + aligned uint4 ST.
// ---------------------------------------------------------------------------
#define BM 128
#define BN 128
#define BK 16
#define LDST 20   // smem row stride in 32-bit words

__device__ __forceinline__ uint32_t f2tf(float x) {
    uint32_t u;
    asm("cvt.rna.tf32.f32 %0, %1;" : "=r"(u) : "f"(x));
    return u;
}

__device__ __forceinline__ void mma_tf32(float c[4],
                                         uint32_t a0, uint32_t a1, uint32_t a2, uint32_t a3,
                                         uint32_t b0, uint32_t b1)
{
    asm volatile(
        "mma.sync.aligned.m16n8k8.row.col.f32.tf32.tf32.f32 "
        "{%0,%1,%2,%3}, {%4,%5,%6,%7}, {%8,%9}, {%0,%1,%2,%3};\n"
        : "+f"(c[0]), "+f"(c[1]), "+f"(c[2]), "+f"(c[3])
        : "r"(a0), "r"(a1), "r"(a2), "r"(a3), "r"(b0), "r"(b1));
}

__global__ void __launch_bounds__(256, 2) tf32gemm_tn(
    const float* __restrict__ A, const float* __restrict__ B,
    float* __restrict__ C, int M, int N, int K)
{
    __shared__ __align__(16) uint32_t As[BM * LDST];
    __shared__ __align__(16) uint32_t Bs[BN * LDST];

    const int tid  = threadIdx.x;
    const int lane = tid & 31;
    const int wid  = tid >> 5;
    const int wm   = wid & 3;    // warp row group: rows wm*32 .. +32
    const int wn   = wid >> 2;   // warp col group: cols wn*64 .. +64

    const int bmBase = blockIdx.y * BM;
    const int bnBase = blockIdx.x * BN;

    // Loader mapping: idx = tid + i*256, row = idx>>2 (0..127), kvec = (idx&3)*4
    const int lrow0 = tid >> 2;           // rows 0..63 (i=0), +64 (i=1)
    const int lk    = (tid & 3) << 2;     // 0,4,8,12

    // Clamped global A row pointers (M edge)
    int ar0 = bmBase + lrow0;       if (ar0 >= M) ar0 = M - 1;
    int ar1 = bmBase + lrow0 + 64;  if (ar1 >= M) ar1 = M - 1;
    const float* Ap0 = A + (size_t)ar0 * K + lk;
    const float* Ap1 = A + (size_t)ar1 * K + lk;
    const float* Bp0 = B + (size_t)(bnBase + lrow0) * K + lk;
    const float* Bp1 = B + (size_t)(bnBase + lrow0 + 64) * K + lk;

    float acc[2][8][4];
#pragma unroll
    for (int mt = 0; mt < 2; mt++)
#pragma unroll
        for (int nt = 0; nt < 8; nt++)
#pragma unroll
            for (int r = 0; r < 4; r++) acc[mt][nt][r] = 0.f;

    // Fragment LDS base indices
    const int gid = lane >> 2;       // group id 0..7
    const int tig = lane & 3;        // thread in group 0..3

    float4 pa0 = *(const float4*)Ap0;
    float4 pa1 = *(const float4*)Ap1;
    float4 pb0 = *(const float4*)Bp0;
    float4 pb1 = *(const float4*)Bp1;

    for (int k0 = 0;;) {
        // Store prefetched tiles to SMEM with RNA tf32 rounding
        {
            uint4 v;
            v.x = f2tf(pa0.x); v.y = f2tf(pa0.y); v.z = f2tf(pa0.z); v.w = f2tf(pa0.w);
            *(uint4*)&As[lrow0 * LDST + lk] = v;
            v.x = f2tf(pa1.x); v.y = f2tf(pa1.y); v.z = f2tf(pa1.z); v.w = f2tf(pa1.w);
            *(uint4*)&As[(lrow0 + 64) * LDST + lk] = v;
            v.x = f2tf(pb0.x); v.y = f2tf(pb0.y); v.z = f2tf(pb0.z); v.w = f2tf(pb0.w);
            *(uint4*)&Bs[lrow0 * LDST + lk] = v;
            v.x = f2tf(pb1.x); v.y = f2tf(pb1.y); v.z = f2tf(pb1.z); v.w = f2tf(pb1.w);
            *(uint4*)&Bs[(lrow0 + 64) * LDST + lk] = v;
        }
        __syncthreads();

        int knext = k0 + BK;
        if (knext < K) {
            pa0 = *(const float4*)(Ap0 + knext);
            pa1 = *(const float4*)(Ap1 + knext);
            pb0 = *(const float4*)(Bp0 + knext);
            pb1 = *(const float4*)(Bp1 + knext);
        }

        // Compute: 2 k-steps of 8
#pragma unroll
        for (int ks = 0; ks < 2; ks++) {
            const int kb = ks * 8;
            uint32_t af[2][4];
#pragma unroll
            for (int mt = 0; mt < 2; mt++) {
                int mrow = wm * 32 + mt * 16 + gid;
                af[mt][0] = As[mrow * LDST + kb + tig];
                af[mt][1] = As[(mrow + 8) * LDST + kb + tig];
                af[mt][2] = As[mrow * LDST + kb + tig + 4];
                af[mt][3] = As[(mrow + 8) * LDST + kb + tig + 4];
            }
            uint32_t bf[8][2];
#pragma unroll
            for (int nt = 0; nt < 8; nt++) {
                int ncol = wn * 64 + nt * 8 + gid;
                bf[nt][0] = Bs[ncol * LDST + kb + tig];
                bf[nt][1] = Bs[ncol * LDST + kb + tig + 4];
            }
#pragma unroll
            for (int mt = 0; mt < 2; mt++)
#pragma unroll
                for (int nt = 0; nt < 8; nt++)
                    mma_tf32(acc[mt][nt], af[mt][0], af[mt][1], af[mt][2], af[mt][3],
                             bf[nt][0], bf[nt][1]);
        }
        __syncthreads();

        k0 = knext;
        if (k0 >= K) break;
    }

    // Epilogue: each mma tile -> rows gid / gid+8, cols 2*tig / +1
#pragma unroll
    for (int mt = 0; mt < 2; mt++) {
        int r0 = bmBase + wm * 32 + mt * 16 + gid;
        int r1 = r0 + 8;
#pragma unroll
        for (int nt = 0; nt < 8; nt++) {
            int col = bnBase + wn * 64 + nt * 8 + tig * 2;
            if (r0 < M)
                *(float2*)(C + (size_t)r0 * N + col) = make_float2(acc[mt][nt][0], acc[mt][nt][1]);
            if (r1 < M)
                *(float2*)(C + (size_t)r1 * N + col) = make_float2(acc[mt][nt][2], acc[mt][nt][3]);
        }
    }
}

// ---------------------------------------------------------------------------
// Per-level fused gate/elementwise kernel (unchanged from round 1).
// ---------------------------------------------------------------------------
__device__ __forceinline__ float sigf(float x) { return 1.f / (1.f + expf(-x)); }
__device__ __forceinline__ float4 f4add(float4 a, float4 b) {
    return make_float4(a.x + b.x, a.y + b.y, a.z + b.z, a.w + b.w);
}

__global__ void __launch_bounds__(256) lstm_level_kernel(
    const float* __restrict__ iofux_b, const float* __restrict__ iofuh_b,
    const float* __restrict__ px_b, float* __restrict__ out,
    int start, int n, int hasPrev)
{
    int idx = blockIdx.x * 256 + threadIdx.x;   // float4 granularity
    int total = n * (H_DIM / 4);
    if (idx >= total) return;

    int j  = idx >> 7;         // node index within level
    int t4 = idx & 127;        // float4 column
    size_t g = (size_t)start + j;

    const float4* gx = (const float4*)(g_iofux + g * GATE5);
    float4 vi = gx[t4];
    float4 vo = gx[128 + t4];
    float4 vf = gx[256 + t4];
    float4 vu = gx[384 + t4];
    float4 vr = gx[512 + t4];

    float4 pc = make_float4(0.f, 0.f, 0.f, 0.f);
    if (hasPrev) {
        const float4* gh = (const float4*)(g_hh + (size_t)(j >> 1) * GATE5);
        vi = f4add(vi, gh[t4]);
        vo = f4add(vo, gh[128 + t4]);
        vf = f4add(vf, gh[256 + t4]);
        vu = f4add(vu, gh[384 + t4]);
        vr = f4add(vr, gh[512 + t4]);
        size_t parent = (g - 1) >> 1;
        pc = ((const float4*)g_c)[parent * 128 + t4];
    }

    const float4* bx = (const float4*)iofux_b;
    const float4* bh = (const float4*)iofuh_b;
    vi = f4add(vi, f4add(bx[t4],       bh[t4]));
    vo = f4add(vo, f4add(bx[128 + t4], bh[128 + t4]));
    vf = f4add(vf, f4add(bx[256 + t4], bh[256 + t4]));
    vu = f4add(vu, f4add(bx[384 + t4], bh[384 + t4]));
    vr = f4add(vr, f4add(bx[512 + t4], bh[512 + t4]));

    float4 px4 = f4add(((const float4*)g_px)[g * 128 + t4],
                       ((const float4*)px_b)[t4]);

    float4 c4, h4;
#define GATE(C) {                                                     \
        float i_ = sigf(vi.C); float o_ = sigf(vo.C);                 \
        float f_ = sigf(vf.C); float u_ = tanhf(vu.C);                \
        float r_ = sigf(vr.C);                                        \
        float c_ = i_ * u_ + f_ * pc.C;                               \
        float h_ = o_ * tanhf(c_);                                    \
        c4.C = c_; h4.C = r_ * h_ + (1.f - r_) * px4.C; }
    GATE(x) GATE(y) GATE(z) GATE(w)
#undef GATE

    ((float4*)g_c)[g * 128 + t4] = c4;
    ((float4*)out)[g * 128 + t4] = h4;
}

// ---------------------------------------------------------------------------
// kernel_launch: 2 big GEMMs + 17 levels (recurrent GEMM + fused gates)
// ---------------------------------------------------------------------------
extern "C" void kernel_launch(void* const* d_in, const int* in_sizes, int n_in,
                              void* d_out, int out_size)
{
    const float* features = (const float*)d_in[0];
    const float* px_w     = (const float*)d_in[1];
    const float* px_b     = (const float*)d_in[2];
    const float* iofux_w  = (const float*)d_in[3];
    const float* iofux_b  = (const float*)d_in[4];
    const float* iofuh_w  = (const float*)d_in[5];
    const float* iofuh_b  = (const float*)d_in[6];
    float* out = (float*)d_out;

    float *iofux_p = nullptr, *px_p = nullptr, *hh_p = nullptr;
    cudaGetSymbolAddress((void**)&iofux_p, g_iofux);
    cudaGetSymbolAddress((void**)&px_p,    g_px);
    cudaGetSymbolAddress((void**)&hh_p,    g_hh);

    dim3 blk(256);

    // Precompute px = feats @ px_w.T   [N_NODES, 512]
    {
        dim3 grid(H_DIM / BN, (N_NODES + BM - 1) / BM);
        tf32gemm_tn<<<grid, blk>>>(features, px_w, px_p, N_NODES, H_DIM, FEAT_DIM);
    }
    // Precompute iofux = feats @ iofux_w.T  [N_NODES, 2560]
    {
        dim3 grid(GATE5 / BN, (N_NODES + BM - 1) / BM);
        tf32gemm_tn<<<grid, blk>>>(features, iofux_w, iofux_p, N_NODES, GATE5, FEAT_DIM);
    }

    // Level-by-level recurrence
    for (int d = 0; d < DEPTH; d++) {
        int n = 1 << d;
        int start = n - 1;
        if (d > 0) {
            int Md = n >> 1;
            int startPrev = Md - 1;
            // hh = prev_h_final @ iofuh_w.T  [Md, 2560]
            dim3 grid(GATE5 / BN, (Md + BM - 1) / BM);
            tf32gemm_tn<<<grid, blk>>>(out + (size_t)startPrev * H_DIM,
                                       iofuh_w, hh_p, Md, GATE5, FEAT_DIM);
        }
        int total = n * (H_DIM / 4);
        int nb = (total + 255) / 256;
        lstm_level_kernel<<<nb, blk>>>(iofux_b, iofuh_b, px_b, out,
                                       start, n, d > 0 ? 1 : 0);
    }
}